// round 16
// baseline (speedup 1.0000x reference)
#include <cuda_runtime.h>
#include <cuda_bf16.h>
#include <mma.h>
#include <cstdint>

// WindowAttention fused kernel (sm_103a host, plain sm_103 PTX target).
// R15: GEMM1 AND GEMM4 on HMMA (wmma bf16 m16n16k16, 3-pass bf16-split).
//      GEMM3 writes its output directly as bf16 hi/lo (A-operand of GEMM4);
//      proj_w staged as col-major B (no transpose). GEMM2/3 mainloops + softmax
//      unchanged (fp32 packed fma.rn.f32x2).

using namespace nvcuda;

#define SCALE_F 0.17677669529663687f   // 32^-0.5

#define LDN 68
#define LDP 132
#define SW(c) ((c) + (((c) & 32) >> 3))

#define OFF_KT 0                       // k_t [128][LDN] -> GEMM4 D scratch [64][LDP]
#define OFF_V  (128*LDN)               // v_t [128][LDN]
#define OFF_QT (2*128*LDN)             // q_t [128][LDN]
#define OFF_AT (3*128*LDN)             // attn_t [256][LDN] -> ph/pl bf16
#define OFF_SC (OFF_AT + 256*LDN)      // softmax scratch [2][256]

// bf16 staging, byte offsets
#define LDKB 136                       // W/Y bf16 leading dim (k)
#define WH_B 69632                     // GEMM1: W hi [128][LDKB] (QT+AT region)
#define WL_B 104448
#define YH_B 139264                    // GEMM1: Y hi [64][LDKB]
#define YL_B 156672                    // ends 174080
#define LDCB 136                       // ph/pl: col-major B, stride between c-cols
#define PH_B 104448                    // GEMM4: proj_w hi [128c][LDCB j] (AT region)
#define PL_B 139264                    //        ends 174080
#define LDOB 72                        // oh/ol leading dim (n), 144B rows
#define OH_B 176128                    // GEMM4 A: o hi [128j][LDOB n] (dedicated)
#define OL_B (OH_B + 18432)
#define SMEM_BYTES (OL_B + 18432)      // 212992 B

typedef unsigned long long u64;

__device__ __forceinline__ u64 pk2(float v) {
    u64 r; asm("mov.b64 %0, {%1, %1};" : "=l"(r) : "f"(v)); return r;
}
__device__ __forceinline__ u64 pkab(float lo, float hi) {
    u64 r; asm("mov.b64 %0, {%1, %2};" : "=l"(r) : "f"(lo), "f"(hi)); return r;
}
__device__ __forceinline__ u64 f2fma(u64 a, u64 b, u64 c) {
    u64 d; asm("fma.rn.f32x2 %0, %1, %2, %3;" : "=l"(d) : "l"(a), "l"(b), "l"(c)); return d;
}
__device__ __forceinline__ u64 f2add(u64 a, u64 b) {
    u64 d; asm("add.rn.f32x2 %0, %1, %2;" : "=l"(d) : "l"(a), "l"(b)); return d;
}
__device__ __forceinline__ void upk2(u64 v, float& lo, float& hi) {
    asm("mov.b64 {%0, %1}, %2;" : "=f"(lo), "=f"(hi) : "l"(v));
}
__device__ __forceinline__ u64 lds2(const float* p) {
    return *reinterpret_cast<const u64*>(p);
}
__device__ __forceinline__ unsigned short f2bf(float f) {
    return __bfloat16_as_ushort(__float2bfloat16(f));
}
__device__ __forceinline__ float bf2f(unsigned short u) {
    return __bfloat162float(__ushort_as_bfloat16(u));
}
// 8 consecutive floats -> packed bf16 hi (16B) + residual lo (16B)
__device__ __forceinline__ void cvt8(const float* f, uint4& H, uint4& L) {
    unsigned int h[4], l[4];
    #pragma unroll
    for (int i = 0; i < 4; ++i) {
        float a = f[2*i], c = f[2*i+1];
        unsigned short ha = f2bf(a), hc = f2bf(c);
        float ra = a - bf2f(ha), rc = c - bf2f(hc);
        unsigned short la = f2bf(ra), lc = f2bf(rc);
        h[i] = (unsigned)ha | ((unsigned)hc << 16);
        l[i] = (unsigned)la | ((unsigned)lc << 16);
    }
    H = make_uint4(h[0], h[1], h[2], h[3]);
    L = make_uint4(l[0], l[1], l[2], l[3]);
}
// 4 floats -> bf16 hi uint2 + residual lo uint2
__device__ __forceinline__ void cvt4(float f0, float f1, float f2, float f3,
                                     uint2& H, uint2& L) {
    unsigned short h0 = f2bf(f0), h1 = f2bf(f1), h2 = f2bf(f2), h3 = f2bf(f3);
    unsigned short l0 = f2bf(f0 - bf2f(h0)), l1 = f2bf(f1 - bf2f(h1));
    unsigned short l2 = f2bf(f2 - bf2f(h2)), l3 = f2bf(f3 - bf2f(h3));
    H = make_uint2((unsigned)h0 | ((unsigned)h1 << 16), (unsigned)h2 | ((unsigned)h3 << 16));
    L = make_uint2((unsigned)l0 | ((unsigned)l1 << 16), (unsigned)l2 | ((unsigned)l3 << 16));
}

__global__ void __launch_bounds__(512, 1)
wattn_kernel(const float* __restrict__ x, const float* __restrict__ y,
             const float* __restrict__ P, const float* __restrict__ maskp,
             const float* __restrict__ qkv_w, const float* __restrict__ qkv_b,
             const float* __restrict__ proj_w, const float* __restrict__ proj_b,
             const float* __restrict__ lam_p, float* __restrict__ out)
{
    extern __shared__ float sm[];
    char* smc = reinterpret_cast<char*>(sm);
    const int b   = blockIdx.x;
    const int tid = threadIdx.x;
    const int wid = tid >> 5;

    __nv_bfloat16* wh = (__nv_bfloat16*)(smc + WH_B);
    __nv_bfloat16* wl = (__nv_bfloat16*)(smc + WL_B);
    __nv_bfloat16* yh = (__nv_bfloat16*)(smc + YH_B);
    __nv_bfloat16* yl = (__nv_bfloat16*)(smc + YL_B);

    // ---- prefetch x into registers (q_t staged after GEMM1) ----
    float4 xr0, xr1, xr2, xr3;
    const int xh = tid >> 7, xnb = (tid >> 3) & 15, xdb = tid & 7;
    {
        const float* xb = x + (size_t)b * 8192 + xh * 2048 + xdb * 4;
        xr0 = *(const float4*)(xb + (4 * xnb + 0) * 32);
        xr1 = *(const float4*)(xb + (4 * xnb + 1) * 32);
        xr2 = *(const float4*)(xb + (4 * xnb + 2) * 32);
        xr3 = *(const float4*)(xb + (4 * xnb + 3) * 32);
    }

    // ---- stage Y -> bf16 hi/lo [64][LDKB] ----
    {
        const int n = tid >> 3, k0 = (tid & 7) << 4;
        const float* yr = y + (size_t)b * 8192 + n * 128 + k0;
        float f[16];
        *(float4*)&f[0]  = *(const float4*)(yr);
        *(float4*)&f[4]  = *(const float4*)(yr + 4);
        *(float4*)&f[8]  = *(const float4*)(yr + 8);
        *(float4*)&f[12] = *(const float4*)(yr + 12);
        #pragma unroll
        for (int u = 0; u < 2; ++u) {
            uint4 H, L; cvt8(&f[8 * u], H, L);
            *(uint4*)(yh + n * LDKB + k0 + 8 * u) = H;
            *(uint4*)(yl + n * LDKB + k0 + 8 * u) = L;
        }
    }
    // ---- stage W half 0 (rows 0..127) ----
    {
        const int r = tid >> 2, k0 = (tid & 3) << 5;
        const float* wr = qkv_w + r * 128 + k0;
        float f[32];
        #pragma unroll
        for (int i = 0; i < 8; ++i) *(float4*)&f[4 * i] = *(const float4*)(wr + 4 * i);
        #pragma unroll
        for (int u = 0; u < 4; ++u) {
            uint4 H, L; cvt8(&f[8 * u], H, L);
            *(uint4*)(wh + r * LDKB + k0 + 8 * u) = H;
            *(uint4*)(wl + r * LDKB + k0 + 8 * u) = L;
        }
    }
    __syncthreads();

    // ---- wmma half 0: D[c][n] = sum_k W[c][k]*y[n][k], c 0..127 -> k_t ----
    {
        const int c0 = (wid >> 1) << 4;
        const int n0a = (wid & 1) << 5, n0b = n0a + 16;
        const int nas = n0a + ((n0a & 32) >> 3), nbs = n0b + ((n0b & 32) >> 3);
        wmma::fragment<wmma::accumulator, 16, 16, 16, float> acc0, acc1;
        wmma::fill_fragment(acc0, 0.0f);
        wmma::fill_fragment(acc1, 0.0f);
        #pragma unroll
        for (int k0 = 0; k0 < 128; k0 += 16) {
            wmma::fragment<wmma::matrix_a, 16, 16, 16, __nv_bfloat16, wmma::row_major> Ah, Al;
            wmma::load_matrix_sync(Ah, wh + c0 * LDKB + k0, LDKB);
            wmma::load_matrix_sync(Al, wl + c0 * LDKB + k0, LDKB);
            wmma::fragment<wmma::matrix_b, 16, 16, 16, __nv_bfloat16, wmma::col_major> Bh, Bl;
            wmma::load_matrix_sync(Bh, yh + n0a * LDKB + k0, LDKB);
            wmma::load_matrix_sync(Bl, yl + n0a * LDKB + k0, LDKB);
            wmma::mma_sync(acc0, Ah, Bh, acc0);
            wmma::mma_sync(acc0, Ah, Bl, acc0);
            wmma::mma_sync(acc0, Al, Bh, acc0);
            wmma::load_matrix_sync(Bh, yh + n0b * LDKB + k0, LDKB);
            wmma::load_matrix_sync(Bl, yl + n0b * LDKB + k0, LDKB);
            wmma::mma_sync(acc1, Ah, Bh, acc1);
            wmma::mma_sync(acc1, Ah, Bl, acc1);
            wmma::mma_sync(acc1, Al, Bh, acc1);
        }
        wmma::store_matrix_sync(&sm[OFF_KT + c0 * LDN + nas], acc0, LDN, wmma::mem_row_major);
        wmma::store_matrix_sync(&sm[OFF_KT + c0 * LDN + nbs], acc1, LDN, wmma::mem_row_major);
    }
    __syncthreads();

    // ---- stage W half 1 (rows 128..255) ----
    {
        const int r = tid >> 2, k0 = (tid & 3) << 5;
        const float* wr = qkv_w + (128 + r) * 128 + k0;
        float f[32];
        #pragma unroll
        for (int i = 0; i < 8; ++i) *(float4*)&f[4 * i] = *(const float4*)(wr + 4 * i);
        #pragma unroll
        for (int u = 0; u < 4; ++u) {
            uint4 H, L; cvt8(&f[8 * u], H, L);
            *(uint4*)(wh + r * LDKB + k0 + 8 * u) = H;
            *(uint4*)(wl + r * LDKB + k0 + 8 * u) = L;
        }
    }
    __syncthreads();

    // ---- wmma half 1: c 128..255 -> v_t ----
    {
        const int c0 = (wid >> 1) << 4;
        const int n0a = (wid & 1) << 5, n0b = n0a + 16;
        const int nas = n0a + ((n0a & 32) >> 3), nbs = n0b + ((n0b & 32) >> 3);
        wmma::fragment<wmma::accumulator, 16, 16, 16, float> acc0, acc1;
        wmma::fill_fragment(acc0, 0.0f);
        wmma::fill_fragment(acc1, 0.0f);
        #pragma unroll
        for (int k0 = 0; k0 < 128; k0 += 16) {
            wmma::fragment<wmma::matrix_a, 16, 16, 16, __nv_bfloat16, wmma::row_major> Ah, Al;
            wmma::load_matrix_sync(Ah, wh + c0 * LDKB + k0, LDKB);
            wmma::load_matrix_sync(Al, wl + c0 * LDKB + k0, LDKB);
            wmma::fragment<wmma::matrix_b, 16, 16, 16, __nv_bfloat16, wmma::col_major> Bh, Bl;
            wmma::load_matrix_sync(Bh, yh + n0a * LDKB + k0, LDKB);
            wmma::load_matrix_sync(Bl, yl + n0a * LDKB + k0, LDKB);
            wmma::mma_sync(acc0, Ah, Bh, acc0);
            wmma::mma_sync(acc0, Ah, Bl, acc0);
            wmma::mma_sync(acc0, Al, Bh, acc0);
            wmma::load_matrix_sync(Bh, yh + n0b * LDKB + k0, LDKB);
            wmma::load_matrix_sync(Bl, yl + n0b * LDKB + k0, LDKB);
            wmma::mma_sync(acc1, Ah, Bh, acc1);
            wmma::mma_sync(acc1, Ah, Bl, acc1);
            wmma::mma_sync(acc1, Al, Bh, acc1);
        }
        wmma::store_matrix_sync(&sm[OFF_V + c0 * LDN + nas], acc0, LDN, wmma::mem_row_major);
        wmma::store_matrix_sync(&sm[OFF_V + c0 * LDN + nbs], acc1, LDN, wmma::mem_row_major);
    }
    __syncthreads();

    // ---- bias fixup for k_t/v_t + stage q_t ----
    {
        const int c2 = tid >> 1;
        const int off = (tid & 1) * 36;
        const float bias = qkv_b[c2];
        u64 bb = pk2(bias);
        float* dp = &sm[OFF_KT + c2 * LDN + off];
        #pragma unroll
        for (int i = 0; i < 16; ++i)
            *(u64*)(dp + 2 * i) = f2add(lds2(dp + 2 * i), bb);
    }
    {
        float* qb = &sm[OFF_QT + (32 * xh + 4 * xdb) * LDN + SW(4 * xnb)];
        *(float4*)(qb + 0 * LDN) = make_float4(xr0.x*SCALE_F, xr1.x*SCALE_F, xr2.x*SCALE_F, xr3.x*SCALE_F);
        *(float4*)(qb + 1 * LDN) = make_float4(xr0.y*SCALE_F, xr1.y*SCALE_F, xr2.y*SCALE_F, xr3.y*SCALE_F);
        *(float4*)(qb + 2 * LDN) = make_float4(xr0.z*SCALE_F, xr1.z*SCALE_F, xr2.z*SCALE_F, xr3.z*SCALE_F);
        *(float4*)(qb + 3 * LDN) = make_float4(xr0.w*SCALE_F, xr1.w*SCALE_F, xr2.w*SCALE_F, xr3.w*SCALE_F);
    }
    __syncthreads();

    // ===== GEMM2: attn_t[h*64+m][n] = sum_d q_t[32h+d][n]*k_t[32h+d][m] =====
    {
        const int h = tid >> 7, rest = tid & 127;
        const int mg = rest >> 3, tr = rest & 7;
        const int m0 = mg << 2, r0 = tr << 3;
        const int r0s = SW(r0), m0s = SW(m0);
        u64 acc[4][4];
        #pragma unroll
        for (int p = 0; p < 4; ++p)
            #pragma unroll
            for (int cc = 0; cc < 4; ++cc) acc[p][cc] = 0ull;
        #pragma unroll 8
        for (int d = 0; d < 32; ++d) {
            const int row = (h << 5) + d;
            const float* ar = &sm[OFF_QT + row * LDN + r0s];
            float4 af0 = *(const float4*)ar;
            float4 af1 = *(const float4*)(ar + 4);
            u64 a0 = pkab(af0.x, af0.y), a1 = pkab(af0.z, af0.w);
            u64 a2 = pkab(af1.x, af1.y), a3 = pkab(af1.z, af1.w);
            float4 bv = *(const float4*)&sm[OFF_KT + row * LDN + m0s];
            float bs[4] = {bv.x, bv.y, bv.z, bv.w};
            #pragma unroll
            for (int cc = 0; cc < 4; ++cc) {
                u64 bb = pk2(bs[cc]);
                acc[0][cc] = f2fma(a0, bb, acc[0][cc]);
                acc[1][cc] = f2fma(a1, bb, acc[1][cc]);
                acc[2][cc] = f2fma(a2, bb, acc[2][cc]);
                acc[3][cc] = f2fma(a3, bb, acc[3][cc]);
            }
        }
        #pragma unroll
        for (int cc = 0; cc < 4; ++cc) {
            const int row = (h << 6) + m0 + cc;
            #pragma unroll
            for (int p = 0; p < 4; ++p)
                *(u64*)&sm[OFF_AT + row * LDN + r0s + 2 * p] = acc[p][cc];
        }
    }
    __syncthreads();

    // ===== Softmax over m with mask + lambda*P; 2 threads per column =====
    {
        const int col = tid & 255, half = tid >> 8;
        const int h = col >> 6, n = col & 63;
        const int m0 = half << 5;
        const int ns = SW(n);
        const float lam = lam_p[0];
        const int w = b & 2047;
        const float4* Pr = (const float4*)(P + ((((size_t)b * 4 + h) * 64 + n) * 64) + m0);
        const float4* Mr = (const float4*)(maskp + (((size_t)w * 64 + n) * 64) + m0);
        const int base = OFF_AT + ((h << 6) + m0) * LDN + ns;
        float v[32];
        float s = 0.f;
        #pragma unroll
        for (int q = 0; q < 8; ++q) {
            float4 pv = Pr[q];
            float4 mv = Mr[q];
            float t0 = sm[base + (4*q+0)*LDN] + mv.x + lam * pv.x;
            float t1 = sm[base + (4*q+1)*LDN] + mv.y + lam * pv.y;
            float t2 = sm[base + (4*q+2)*LDN] + mv.z + lam * pv.z;
            float t3 = sm[base + (4*q+3)*LDN] + mv.w + lam * pv.w;
            v[4*q+0] = __expf(t0); v[4*q+1] = __expf(t1);
            v[4*q+2] = __expf(t2); v[4*q+3] = __expf(t3);
            s += v[4*q+0] + v[4*q+1] + v[4*q+2] + v[4*q+3];
        }
        sm[OFF_SC + (half << 8) + col] = s;
        __syncthreads();
        const float inv = 1.0f / (sm[OFF_SC + col] + sm[OFF_SC + 256 + col]);
        #pragma unroll
        for (int m = 0; m < 32; ++m) sm[base + m * LDN] = v[m] * inv;
    }
    __syncthreads();

    // ===== GEMM3: o[j][n] = sum_m attn_t[h*64+m][n] * v_t[j][m], h=j/32 =====
    // writeback converts to bf16 hi/lo -> oh/ol [j][LDOB n] (A of GEMM4)
    {
        const int nr = tid & 15, jc = tid >> 4;
        const int n0 = nr << 2, j0 = jc << 2, h = jc >> 3;
        const int n0s = SW(n0);
        u64 acc[2][4];
        #pragma unroll
        for (int p = 0; p < 2; ++p)
            #pragma unroll
            for (int cc = 0; cc < 4; ++cc) acc[p][cc] = 0ull;
        #pragma unroll 16
        for (int m = 0; m < 64; ++m) {
            const int ms = SW(m);
            float4 af = *(const float4*)&sm[OFF_AT + ((h << 6) + m) * LDN + n0s];
            u64 a0 = pkab(af.x, af.y), a1 = pkab(af.z, af.w);
            #pragma unroll
            for (int cc = 0; cc < 4; ++cc) {
                u64 bb = pk2(sm[OFF_V + (j0 + cc) * LDN + ms]);
                acc[0][cc] = f2fma(a0, bb, acc[0][cc]);
                acc[1][cc] = f2fma(a1, bb, acc[1][cc]);
            }
        }
        #pragma unroll
        for (int cc = 0; cc < 4; ++cc) {
            float f0, f1, f2, f3;
            upk2(acc[0][cc], f0, f1);
            upk2(acc[1][cc], f2, f3);
            uint2 H, L; cvt4(f0, f1, f2, f3, H, L);
            const int ob = (j0 + cc) * (LDOB * 2) + n0 * 2;
            *(uint2*)(smc + OH_B + ob) = H;
            *(uint2*)(smc + OL_B + ob) = L;
        }
    }
    __syncthreads();

    // ===== Stage proj_w -> bf16 hi/lo ph/pl [128 c][LDCB j] (col-major B) =====
    {
        __nv_bfloat16* ph = (__nv_bfloat16*)(smc + PH_B);
        __nv_bfloat16* pl = (__nv_bfloat16*)(smc + PL_B);
        const int r = tid >> 2, k0 = (tid & 3) << 5;
        const float* pr = proj_w + r * 128 + k0;
        float f[32];
        #pragma unroll
        for (int i = 0; i < 8; ++i) *(float4*)&f[4 * i] = *(const float4*)(pr + 4 * i);
        #pragma unroll
        for (int u = 0; u < 4; ++u) {
            uint4 H, L; cvt8(&f[8 * u], H, L);
            *(uint4*)(ph + r * LDCB + k0 + 8 * u) = H;
            *(uint4*)(pl + r * LDCB + k0 + 8 * u) = L;
        }
    }
    __syncthreads();

    // ===== GEMM4 (wmma): D[n][c] = sum_j o[n][j] * proj_w[c][j] =====
    // A col-major from oh/ol (ld LDOB), B col-major from ph/pl (ld LDCB).
    {
        __nv_bfloat16* oh = (__nv_bfloat16*)(smc + OH_B);
        __nv_bfloat16* ol = (__nv_bfloat16*)(smc + OL_B);
        __nv_bfloat16* ph = (__nv_bfloat16*)(smc + PH_B);
        __nv_bfloat16* pl = (__nv_bfloat16*)(smc + PL_B);
        const int n0 = (wid & 3) << 4;
        const int c0 = (wid >> 2) << 5, c1 = c0 + 16;
        wmma::fragment<wmma::accumulator, 16, 16, 16, float> acc0, acc1;
        wmma::fill_fragment(acc0, 0.0f);
        wmma::fill_fragment(acc1, 0.0f);
        #pragma unroll
        for (int j0 = 0; j0 < 128; j0 += 16) {
            wmma::fragment<wmma::matrix_a, 16, 16, 16, __nv_bfloat16, wmma::col_major> Ah, Al;
            wmma::load_matrix_sync(Ah, oh + j0 * LDOB + n0, LDOB);
            wmma::load_matrix_sync(Al, ol + j0 * LDOB + n0, LDOB);
            wmma::fragment<wmma::matrix_b, 16, 16, 16, __nv_bfloat16, wmma::col_major> Bh, Bl;
            wmma::load_matrix_sync(Bh, ph + c0 * LDCB + j0, LDCB);
            wmma::load_matrix_sync(Bl, pl + c0 * LDCB + j0, LDCB);
            wmma::mma_sync(acc0, Ah, Bh, acc0);
            wmma::mma_sync(acc0, Ah, Bl, acc0);
            wmma::mma_sync(acc0, Al, Bh, acc0);
            wmma::load_matrix_sync(Bh, ph + c1 * LDCB + j0, LDCB);
            wmma::load_matrix_sync(Bl, pl + c1 * LDCB + j0, LDCB);
            wmma::mma_sync(acc1, Ah, Bh, acc1);
            wmma::mma_sync(acc1, Ah, Bl, acc1);
            wmma::mma_sync(acc1, Al, Bh, acc1);
        }
        // D scratch in dead k_t region: [64 n][LDP c]
        wmma::store_matrix_sync(&sm[OFF_KT + n0 * LDP + c0], acc0, LDP, wmma::mem_row_major);
        wmma::store_matrix_sync(&sm[OFF_KT + n0 * LDP + c1], acc1, LDP, wmma::mem_row_major);
    }
    __syncthreads();

    // ===== bias + store out =====
    {
        const int n = tid >> 3, cq = (tid & 7) << 4;
        const float* sp = &sm[OFF_KT + n * LDP + cq];
        float* ob = out + (size_t)b * 8192 + n * 128 + cq;
        #pragma unroll
        for (int i = 0; i < 4; ++i) {
            float4 dv = *(const float4*)(sp + 4 * i);
            float4 pb = *(const float4*)(proj_b + cq + 4 * i);
            *(float4*)(ob + 4 * i) = make_float4(dv.x + pb.x, dv.y + pb.y,
                                                 dv.z + pb.z, dv.w + pb.w);
        }
    }
}

extern "C" void kernel_launch(void* const* d_in, const int* in_sizes, int n_in,
                              void* d_out, int out_size)
{
    const float* x      = (const float*)d_in[0];
    const float* y      = (const float*)d_in[1];
    const float* P      = (const float*)d_in[2];
    const float* maskp  = (const float*)d_in[3];
    const float* qkv_w  = (const float*)d_in[4];
    const float* qkv_b  = (const float*)d_in[5];
    const float* proj_w = (const float*)d_in[6];
    const float* proj_b = (const float*)d_in[7];
    const float* lam    = (const float*)d_in[8];
    float* out = (float*)d_out;

    cudaFuncSetAttribute(wattn_kernel,
                         cudaFuncAttributeMaxDynamicSharedMemorySize, SMEM_BYTES);
    wattn_kernel<<<4096, 512, SMEM_BYTES>>>(x, y, P, maskp, qkv_w, qkv_b,
                                            proj_w, proj_b, lam, out);
}

// round 17
// speedup vs baseline: 1.0435x; 1.0435x over previous
#include <cuda_runtime.h>
#include <cuda_bf16.h>
#include <mma.h>
#include <cstdint>

// WindowAttention fused kernel (sm_103a host, plain sm_103 PTX target).
// R16: GEMM1+GEMM4 on HMMA (wmma bf16, 3-pass split) with interleaved
//      accumulator chains (2-way tensor ILP); proj_w LDG hidden under GEMM3;
//      bias folded into GEMM4 as rank-1 mma; D stored directly to global.

using namespace nvcuda;

#define SCALE_F 0.17677669529663687f   // 32^-0.5

#define LDN 68
#define SW(c) ((c) + (((c) & 32) >> 3))

#define OFF_KT 0                       // k_t [128][LDN]; dead after GEMM2 -> ph
#define OFF_V  (128*LDN)               // v_t [128][LDN]
#define OFF_QT (2*128*LDN)             // q_t [128][LDN]; dead after GEMM2 -> pl
#define OFF_AT (3*128*LDN)             // attn_t [256][LDN]
#define OFF_SC (OFF_AT + 256*LDN)      // softmax scratch [2][256]

// byte offsets
#define LDKB 136                       // GEMM1 W/Y bf16 leading dim (k)
#define WH_B 69632                     // GEMM1: W hi [128][LDKB] (QT+AT dead region)
#define WL_B 104448
#define YH_B 139264                    // GEMM1: Y hi [64][LDKB]
#define YL_B 156672                    // ends 174080
#define LDCB 136                       // GEMM4 B: ph/pl [128 c][LDCB j]
#define PH_B 0                         // k_t region (dead after GEMM2)
#define PL_B 69632                     // q_t region (dead after GEMM2)
#define LDOB 72                        // oh/ol leading dim (n)
#define OH_B 176128                    // GEMM4 A: o hi [128 j][LDOB n]
#define OL_B 194560
#define ONES_B 212992                  // A-ones 16x16 bf16 col-major (512 B)
#define PBH_B 213504                   // bias B hi [128 c][16] col-major (4 KB)
#define PBL_B 217600                   // bias B lo
#define SMEM_BYTES 221696

typedef unsigned long long u64;

__device__ __forceinline__ u64 pk2(float v) {
    u64 r; asm("mov.b64 %0, {%1, %1};" : "=l"(r) : "f"(v)); return r;
}
__device__ __forceinline__ u64 pkab(float lo, float hi) {
    u64 r; asm("mov.b64 %0, {%1, %2};" : "=l"(r) : "f"(lo), "f"(hi)); return r;
}
__device__ __forceinline__ u64 f2fma(u64 a, u64 b, u64 c) {
    u64 d; asm("fma.rn.f32x2 %0, %1, %2, %3;" : "=l"(d) : "l"(a), "l"(b), "l"(c)); return d;
}
__device__ __forceinline__ u64 f2add(u64 a, u64 b) {
    u64 d; asm("add.rn.f32x2 %0, %1, %2;" : "=l"(d) : "l"(a), "l"(b)); return d;
}
__device__ __forceinline__ void upk2(u64 v, float& lo, float& hi) {
    asm("mov.b64 {%0, %1}, %2;" : "=f"(lo), "=f"(hi) : "l"(v));
}
__device__ __forceinline__ u64 lds2(const float* p) {
    return *reinterpret_cast<const u64*>(p);
}
__device__ __forceinline__ unsigned short f2bf(float f) {
    return __bfloat16_as_ushort(__float2bfloat16(f));
}
__device__ __forceinline__ float bf2f(unsigned short u) {
    return __bfloat162float(__ushort_as_bfloat16(u));
}
__device__ __forceinline__ void cvt8(const float* f, uint4& H, uint4& L) {
    unsigned int h[4], l[4];
    #pragma unroll
    for (int i = 0; i < 4; ++i) {
        float a = f[2*i], c = f[2*i+1];
        unsigned short ha = f2bf(a), hc = f2bf(c);
        float ra = a - bf2f(ha), rc = c - bf2f(hc);
        unsigned short la = f2bf(ra), lc = f2bf(rc);
        h[i] = (unsigned)ha | ((unsigned)hc << 16);
        l[i] = (unsigned)la | ((unsigned)lc << 16);
    }
    H = make_uint4(h[0], h[1], h[2], h[3]);
    L = make_uint4(l[0], l[1], l[2], l[3]);
}
__device__ __forceinline__ void cvt4(float f0, float f1, float f2, float f3,
                                     uint2& H, uint2& L) {
    unsigned short h0 = f2bf(f0), h1 = f2bf(f1), h2 = f2bf(f2), h3 = f2bf(f3);
    unsigned short l0 = f2bf(f0 - bf2f(h0)), l1 = f2bf(f1 - bf2f(h1));
    unsigned short l2 = f2bf(f2 - bf2f(h2)), l3 = f2bf(f3 - bf2f(h3));
    H = make_uint2((unsigned)h0 | ((unsigned)h1 << 16), (unsigned)h2 | ((unsigned)h3 << 16));
    L = make_uint2((unsigned)l0 | ((unsigned)l1 << 16), (unsigned)l2 | ((unsigned)l3 << 16));
}

__global__ void __launch_bounds__(512, 1)
wattn_kernel(const float* __restrict__ x, const float* __restrict__ y,
             const float* __restrict__ P, const float* __restrict__ maskp,
             const float* __restrict__ qkv_w, const float* __restrict__ qkv_b,
             const float* __restrict__ proj_w, const float* __restrict__ proj_b,
             const float* __restrict__ lam_p, float* __restrict__ out)
{
    extern __shared__ float sm[];
    char* smc = reinterpret_cast<char*>(sm);
    const int b   = blockIdx.x;
    const int tid = threadIdx.x;
    const int wid = tid >> 5;

    __nv_bfloat16* wh = (__nv_bfloat16*)(smc + WH_B);
    __nv_bfloat16* wl = (__nv_bfloat16*)(smc + WL_B);
    __nv_bfloat16* yh = (__nv_bfloat16*)(smc + YH_B);
    __nv_bfloat16* yl = (__nv_bfloat16*)(smc + YL_B);

    // ---- prefetch x into registers ----
    float4 xr0, xr1, xr2, xr3;
    const int xh = tid >> 7, xnb = (tid >> 3) & 15, xdb = tid & 7;
    {
        const float* xb = x + (size_t)b * 8192 + xh * 2048 + xdb * 4;
        xr0 = *(const float4*)(xb + (4 * xnb + 0) * 32);
        xr1 = *(const float4*)(xb + (4 * xnb + 1) * 32);
        xr2 = *(const float4*)(xb + (4 * xnb + 2) * 32);
        xr3 = *(const float4*)(xb + (4 * xnb + 3) * 32);
    }

    // ---- stage Y -> bf16 hi/lo ----
    {
        const int n = tid >> 3, k0 = (tid & 7) << 4;
        const float* yr = y + (size_t)b * 8192 + n * 128 + k0;
        float f[16];
        *(float4*)&f[0]  = *(const float4*)(yr);
        *(float4*)&f[4]  = *(const float4*)(yr + 4);
        *(float4*)&f[8]  = *(const float4*)(yr + 8);
        *(float4*)&f[12] = *(const float4*)(yr + 12);
        #pragma unroll
        for (int u = 0; u < 2; ++u) {
            uint4 H, L; cvt8(&f[8 * u], H, L);
            *(uint4*)(yh + n * LDKB + k0 + 8 * u) = H;
            *(uint4*)(yl + n * LDKB + k0 + 8 * u) = L;
        }
    }
    // ---- stage W half 0 ----
    {
        const int r = tid >> 2, k0 = (tid & 3) << 5;
        const float* wr = qkv_w + r * 128 + k0;
        float f[32];
        #pragma unroll
        for (int i = 0; i < 8; ++i) *(float4*)&f[4 * i] = *(const float4*)(wr + 4 * i);
        #pragma unroll
        for (int u = 0; u < 4; ++u) {
            uint4 H, L; cvt8(&f[8 * u], H, L);
            *(uint4*)(wh + r * LDKB + k0 + 8 * u) = H;
            *(uint4*)(wl + r * LDKB + k0 + 8 * u) = L;
        }
    }
    __syncthreads();

    // ---- wmma half 0 -> k_t (interleaved acc chains) ----
    {
        const int c0 = (wid >> 1) << 4;
        const int n0a = (wid & 1) << 5, n0b = n0a + 16;
        const int nas = n0a + ((n0a & 32) >> 3), nbs = n0b + ((n0b & 32) >> 3);
        wmma::fragment<wmma::accumulator, 16, 16, 16, float> acc0, acc1;
        wmma::fill_fragment(acc0, 0.0f);
        wmma::fill_fragment(acc1, 0.0f);
        #pragma unroll
        for (int k0 = 0; k0 < 128; k0 += 16) {
            wmma::fragment<wmma::matrix_a, 16, 16, 16, __nv_bfloat16, wmma::row_major> Ah, Al;
            wmma::load_matrix_sync(Ah, wh + c0 * LDKB + k0, LDKB);
            wmma::load_matrix_sync(Al, wl + c0 * LDKB + k0, LDKB);
            wmma::fragment<wmma::matrix_b, 16, 16, 16, __nv_bfloat16, wmma::col_major> Bh0, Bl0, Bh1, Bl1;
            wmma::load_matrix_sync(Bh0, yh + n0a * LDKB + k0, LDKB);
            wmma::load_matrix_sync(Bl0, yl + n0a * LDKB + k0, LDKB);
            wmma::load_matrix_sync(Bh1, yh + n0b * LDKB + k0, LDKB);
            wmma::load_matrix_sync(Bl1, yl + n0b * LDKB + k0, LDKB);
            wmma::mma_sync(acc0, Ah, Bh0, acc0);
            wmma::mma_sync(acc1, Ah, Bh1, acc1);
            wmma::mma_sync(acc0, Ah, Bl0, acc0);
            wmma::mma_sync(acc1, Ah, Bl1, acc1);
            wmma::mma_sync(acc0, Al, Bh0, acc0);
            wmma::mma_sync(acc1, Al, Bh1, acc1);
        }
        wmma::store_matrix_sync(&sm[OFF_KT + c0 * LDN + nas], acc0, LDN, wmma::mem_row_major);
        wmma::store_matrix_sync(&sm[OFF_KT + c0 * LDN + nbs], acc1, LDN, wmma::mem_row_major);
    }
    __syncthreads();

    // ---- stage W half 1 ----
    {
        const int r = tid >> 2, k0 = (tid & 3) << 5;
        const float* wr = qkv_w + (128 + r) * 128 + k0;
        float f[32];
        #pragma unroll
        for (int i = 0; i < 8; ++i) *(float4*)&f[4 * i] = *(const float4*)(wr + 4 * i);
        #pragma unroll
        for (int u = 0; u < 4; ++u) {
            uint4 H, L; cvt8(&f[8 * u], H, L);
            *(uint4*)(wh + r * LDKB + k0 + 8 * u) = H;
            *(uint4*)(wl + r * LDKB + k0 + 8 * u) = L;
        }
    }
    __syncthreads();

    // ---- wmma half 1 -> v_t ----
    {
        const int c0 = (wid >> 1) << 4;
        const int n0a = (wid & 1) << 5, n0b = n0a + 16;
        const int nas = n0a + ((n0a & 32) >> 3), nbs = n0b + ((n0b & 32) >> 3);
        wmma::fragment<wmma::accumulator, 16, 16, 16, float> acc0, acc1;
        wmma::fill_fragment(acc0, 0.0f);
        wmma::fill_fragment(acc1, 0.0f);
        #pragma unroll
        for (int k0 = 0; k0 < 128; k0 += 16) {
            wmma::fragment<wmma::matrix_a, 16, 16, 16, __nv_bfloat16, wmma::row_major> Ah, Al;
            wmma::load_matrix_sync(Ah, wh + c0 * LDKB + k0, LDKB);
            wmma::load_matrix_sync(Al, wl + c0 * LDKB + k0, LDKB);
            wmma::fragment<wmma::matrix_b, 16, 16, 16, __nv_bfloat16, wmma::col_major> Bh0, Bl0, Bh1, Bl1;
            wmma::load_matrix_sync(Bh0, yh + n0a * LDKB + k0, LDKB);
            wmma::load_matrix_sync(Bl0, yl + n0a * LDKB + k0, LDKB);
            wmma::load_matrix_sync(Bh1, yh + n0b * LDKB + k0, LDKB);
            wmma::load_matrix_sync(Bl1, yl + n0b * LDKB + k0, LDKB);
            wmma::mma_sync(acc0, Ah, Bh0, acc0);
            wmma::mma_sync(acc1, Ah, Bh1, acc1);
            wmma::mma_sync(acc0, Ah, Bl0, acc0);
            wmma::mma_sync(acc1, Ah, Bl1, acc1);
            wmma::mma_sync(acc0, Al, Bh0, acc0);
            wmma::mma_sync(acc1, Al, Bh1, acc1);
        }
        wmma::store_matrix_sync(&sm[OFF_V + c0 * LDN + nas], acc0, LDN, wmma::mem_row_major);
        wmma::store_matrix_sync(&sm[OFF_V + c0 * LDN + nbs], acc1, LDN, wmma::mem_row_major);
    }
    __syncthreads();

    // ---- bias fixup k_t/v_t + stage q_t + stage bias-mma blocks ----
    {
        const int c2 = tid >> 1;
        const int off = (tid & 1) * 36;
        const float bias = qkv_b[c2];
        u64 bb = pk2(bias);
        float* dp = &sm[OFF_KT + c2 * LDN + off];
        #pragma unroll
        for (int i = 0; i < 16; ++i)
            *(u64*)(dp + 2 * i) = f2add(lds2(dp + 2 * i), bb);
    }
    {
        float* qb = &sm[OFF_QT + (32 * xh + 4 * xdb) * LDN + SW(4 * xnb)];
        *(float4*)(qb + 0 * LDN) = make_float4(xr0.x*SCALE_F, xr1.x*SCALE_F, xr2.x*SCALE_F, xr3.x*SCALE_F);
        *(float4*)(qb + 1 * LDN) = make_float4(xr0.y*SCALE_F, xr1.y*SCALE_F, xr2.y*SCALE_F, xr3.y*SCALE_F);
        *(float4*)(qb + 2 * LDN) = make_float4(xr0.z*SCALE_F, xr1.z*SCALE_F, xr2.z*SCALE_F, xr3.z*SCALE_F);
        *(float4*)(qb + 3 * LDN) = make_float4(xr0.w*SCALE_F, xr1.w*SCALE_F, xr2.w*SCALE_F, xr3.w*SCALE_F);
    }
    if (tid < 128) {          // bias B blocks: col-major [c][16], bias at j'=0
        const float pv = proj_b[tid];
        unsigned short h = f2bf(pv);
        unsigned short l = f2bf(pv - bf2f(h));
        __nv_bfloat16* ph_ = (__nv_bfloat16*)(smc + PBH_B) + tid * 16;
        __nv_bfloat16* pl_ = (__nv_bfloat16*)(smc + PBL_B) + tid * 16;
        uint4 z = make_uint4(0, 0, 0, 0);
        *(uint4*)ph_ = z; *(uint4*)(ph_ + 8) = z;
        *(uint4*)pl_ = z; *(uint4*)(pl_ + 8) = z;
        ph_[0] = __ushort_as_bfloat16(h);
        pl_[0] = __ushort_as_bfloat16(l);
    } else if (tid < 144) {   // A-ones block: col-major 16x16, column 0 = 1.0
        const int j = tid - 128;
        __nv_bfloat16* on_ = (__nv_bfloat16*)(smc + ONES_B) + j * 16;
        uint4 v = (j == 0) ? make_uint4(0x3F803F80u, 0x3F803F80u, 0x3F803F80u, 0x3F803F80u)
                           : make_uint4(0, 0, 0, 0);
        *(uint4*)on_ = v; *(uint4*)(on_ + 8) = v;
    }
    __syncthreads();

    // ===== GEMM2: attn_t[h*64+m][n] = sum_d q_t[32h+d][n]*k_t[32h+d][m] =====
    {
        const int h = tid >> 7, rest = tid & 127;
        const int mg = rest >> 3, tr = rest & 7;
        const int m0 = mg << 2, r0 = tr << 3;
        const int r0s = SW(r0), m0s = SW(m0);
        u64 acc[4][4];
        #pragma unroll
        for (int p = 0; p < 4; ++p)
            #pragma unroll
            for (int cc = 0; cc < 4; ++cc) acc[p][cc] = 0ull;
        #pragma unroll 8
        for (int d = 0; d < 32; ++d) {
            const int row = (h << 5) + d;
            const float* ar = &sm[OFF_QT + row * LDN + r0s];
            float4 af0 = *(const float4*)ar;
            float4 af1 = *(const float4*)(ar + 4);
            u64 a0 = pkab(af0.x, af0.y), a1 = pkab(af0.z, af0.w);
            u64 a2 = pkab(af1.x, af1.y), a3 = pkab(af1.z, af1.w);
            float4 bv = *(const float4*)&sm[OFF_KT + row * LDN + m0s];
            float bs[4] = {bv.x, bv.y, bv.z, bv.w};
            #pragma unroll
            for (int cc = 0; cc < 4; ++cc) {
                u64 bb = pk2(bs[cc]);
                acc[0][cc] = f2fma(a0, bb, acc[0][cc]);
                acc[1][cc] = f2fma(a1, bb, acc[1][cc]);
                acc[2][cc] = f2fma(a2, bb, acc[2][cc]);
                acc[3][cc] = f2fma(a3, bb, acc[3][cc]);
            }
        }
        #pragma unroll
        for (int cc = 0; cc < 4; ++cc) {
            const int row = (h << 6) + m0 + cc;
            #pragma unroll
            for (int p = 0; p < 4; ++p)
                *(u64*)&sm[OFF_AT + row * LDN + r0s + 2 * p] = acc[p][cc];
        }
    }
    __syncthreads();

    // ===== Softmax over m with mask + lambda*P; 2 threads per column =====
    {
        const int col = tid & 255, half = tid >> 8;
        const int h = col >> 6, n = col & 63;
        const int m0 = half << 5;
        const int ns = SW(n);
        const float lam = lam_p[0];
        const int w = b & 2047;
        const float4* Pr = (const float4*)(P + ((((size_t)b * 4 + h) * 64 + n) * 64) + m0);
        const float4* Mr = (const float4*)(maskp + (((size_t)w * 64 + n) * 64) + m0);
        const int base = OFF_AT + ((h << 6) + m0) * LDN + ns;
        float v[32];
        float s = 0.f;
        #pragma unroll
        for (int q = 0; q < 8; ++q) {
            float4 pv = Pr[q];
            float4 mv = Mr[q];
            float t0 = sm[base + (4*q+0)*LDN] + mv.x + lam * pv.x;
            float t1 = sm[base + (4*q+1)*LDN] + mv.y + lam * pv.y;
            float t2 = sm[base + (4*q+2)*LDN] + mv.z + lam * pv.z;
            float t3 = sm[base + (4*q+3)*LDN] + mv.w + lam * pv.w;
            v[4*q+0] = __expf(t0); v[4*q+1] = __expf(t1);
            v[4*q+2] = __expf(t2); v[4*q+3] = __expf(t3);
            s += v[4*q+0] + v[4*q+1] + v[4*q+2] + v[4*q+3];
        }
        sm[OFF_SC + (half << 8) + col] = s;
        __syncthreads();
        const float inv = 1.0f / (sm[OFF_SC + col] + sm[OFF_SC + 256 + col]);
        #pragma unroll
        for (int m = 0; m < 32; ++m) sm[base + m * LDN] = v[m] * inv;
    }
    __syncthreads();

    // ===== GEMM3 + proj_w staging (LDGs issued first, hidden under compute) ====
    {
        // prefetch proj_w row segment (global)
        const int pr_r = tid >> 2, pr_k0 = (tid & 3) << 5;
        const float* prw = proj_w + pr_r * 128 + pr_k0;
        float pf[32];
        #pragma unroll
        for (int i = 0; i < 8; ++i) *(float4*)&pf[4 * i] = *(const float4*)(prw + 4 * i);

        // GEMM3: o[j][n] = sum_m attn_t[h*64+m][n] * v_t[j][m]
        const int nr = tid & 15, jc = tid >> 4;
        const int n0 = nr << 2, j0 = jc << 2, h = jc >> 3;
        const int n0s = SW(n0);
        u64 acc[2][4];
        #pragma unroll
        for (int p = 0; p < 2; ++p)
            #pragma unroll
            for (int cc = 0; cc < 4; ++cc) acc[p][cc] = 0ull;
        #pragma unroll 16
        for (int m = 0; m < 64; ++m) {
            const int ms = SW(m);
            float4 af = *(const float4*)&sm[OFF_AT + ((h << 6) + m) * LDN + n0s];
            u64 a0 = pkab(af.x, af.y), a1 = pkab(af.z, af.w);
            #pragma unroll
            for (int cc = 0; cc < 4; ++cc) {
                u64 bb = pk2(sm[OFF_V + (j0 + cc) * LDN + ms]);
                acc[0][cc] = f2fma(a0, bb, acc[0][cc]);
                acc[1][cc] = f2fma(a1, bb, acc[1][cc]);
            }
        }
        // writeback o as bf16 hi/lo (A of GEMM4)
        #pragma unroll
        for (int cc = 0; cc < 4; ++cc) {
            float f0, f1, f2, f3;
            upk2(acc[0][cc], f0, f1);
            upk2(acc[1][cc], f2, f3);
            uint2 H, L; cvt4(f0, f1, f2, f3, H, L);
            const int ob = (j0 + cc) * (LDOB * 2) + n0 * 2;
            *(uint2*)(smc + OH_B + ob) = H;
            *(uint2*)(smc + OL_B + ob) = L;
        }
        // stage proj_w -> ph (k_t region) / pl (q_t region), both dead
        __nv_bfloat16* ph = (__nv_bfloat16*)(smc + PH_B);
        __nv_bfloat16* pl = (__nv_bfloat16*)(smc + PL_B);
        #pragma unroll
        for (int u = 0; u < 4; ++u) {
            uint4 H, L; cvt8(&pf[8 * u], H, L);
            *(uint4*)(ph + pr_r * LDCB + pr_k0 + 8 * u) = H;
            *(uint4*)(pl + pr_r * LDCB + pr_k0 + 8 * u) = L;
        }
    }
    __syncthreads();

    // ===== GEMM4 (wmma): D[n][c] = sum_j o[n][j]*proj_w[c][j] + proj_b[c] ====
    {
        __nv_bfloat16* oh = (__nv_bfloat16*)(smc + OH_B);
        __nv_bfloat16* ol = (__nv_bfloat16*)(smc + OL_B);
        __nv_bfloat16* ph = (__nv_bfloat16*)(smc + PH_B);
        __nv_bfloat16* pl = (__nv_bfloat16*)(smc + PL_B);
        const int n0 = (wid & 3) << 4;
        const int c0 = (wid >> 2) << 5, c1 = c0 + 16;
        wmma::fragment<wmma::accumulator, 16, 16, 16, float> acc0, acc1;
        wmma::fill_fragment(acc0, 0.0f);
        wmma::fill_fragment(acc1, 0.0f);
        #pragma unroll
        for (int j0 = 0; j0 < 128; j0 += 16) {
            wmma::fragment<wmma::matrix_a, 16, 16, 16, __nv_bfloat16, wmma::col_major> Ah, Al;
            wmma::load_matrix_sync(Ah, oh + j0 * LDOB + n0, LDOB);
            wmma::load_matrix_sync(Al, ol + j0 * LDOB + n0, LDOB);
            wmma::fragment<wmma::matrix_b, 16, 16, 16, __nv_bfloat16, wmma::col_major> Bh0, Bl0, Bh1, Bl1;
            wmma::load_matrix_sync(Bh0, ph + c0 * LDCB + j0, LDCB);
            wmma::load_matrix_sync(Bl0, pl + c0 * LDCB + j0, LDCB);
            wmma::load_matrix_sync(Bh1, ph + c1 * LDCB + j0, LDCB);
            wmma::load_matrix_sync(Bl1, pl + c1 * LDCB + j0, LDCB);
            wmma::mma_sync(acc0, Ah, Bh0, acc0);
            wmma::mma_sync(acc1, Ah, Bh1, acc1);
            wmma::mma_sync(acc0, Ah, Bl0, acc0);
            wmma::mma_sync(acc1, Ah, Bl1, acc1);
            wmma::mma_sync(acc0, Al, Bh0, acc0);
            wmma::mma_sync(acc1, Al, Bh1, acc1);
        }
        // bias via rank-1 mma: A-ones (col 0) x B-bias (row 0)
        {
            __nv_bfloat16* on_ = (__nv_bfloat16*)(smc + ONES_B);
            __nv_bfloat16* pbh = (__nv_bfloat16*)(smc + PBH_B);
            __nv_bfloat16* pbl = (__nv_bfloat16*)(smc + PBL_B);
            wmma::fragment<wmma::matrix_a, 16, 16, 16, __nv_bfloat16, wmma::col_major> Ao;
            wmma::load_matrix_sync(Ao, on_, 16);
            wmma::fragment<wmma::matrix_b, 16, 16, 16, __nv_bfloat16, wmma::col_major> Bb0, Bb1, Bc0, Bc1;
            wmma::load_matrix_sync(Bb0, pbh + c0 * 16, 16);
            wmma::load_matrix_sync(Bb1, pbh + c1 * 16, 16);
            wmma::load_matrix_sync(Bc0, pbl + c0 * 16, 16);
            wmma::load_matrix_sync(Bc1, pbl + c1 * 16, 16);
            wmma::mma_sync(acc0, Ao, Bb0, acc0);
            wmma::mma_sync(acc1, Ao, Bb1, acc1);
            wmma::mma_sync(acc0, Ao, Bc0, acc0);
            wmma::mma_sync(acc1, Ao, Bc1, acc1);
        }
        float* ob = out + (size_t)b * 8192;
        wmma::store_matrix_sync(ob + n0 * 128 + c0, acc0, 128, wmma::mem_row_major);
        wmma::store_matrix_sync(ob + n0 * 128 + c1, acc1, 128, wmma::mem_row_major);
    }
}

extern "C" void kernel_launch(void* const* d_in, const int* in_sizes, int n_in,
                              void* d_out, int out_size)
{
    const float* x      = (const float*)d_in[0];
    const float* y      = (const float*)d_in[1];
    const float* P      = (const float*)d_in[2];
    const float* maskp  = (const float*)d_in[3];
    const float* qkv_w  = (const float*)d_in[4];
    const float* qkv_b  = (const float*)d_in[5];
    const float* proj_w = (const float*)d_in[6];
    const float* proj_b = (const float*)d_in[7];
    const float* lam    = (const float*)d_in[8];
    float* out = (float*)d_out;

    cudaFuncSetAttribute(wattn_kernel,
                         cudaFuncAttributeMaxDynamicSharedMemorySize, SMEM_BYTES);
    wattn_kernel<<<4096, 512, SMEM_BYTES>>>(x, y, P, maskp, qkv_w, qkv_b,
                                            proj_w, proj_b, lam, out);
}